// round 15
// baseline (speedup 1.0000x reference)
#include <cuda_runtime.h>
#include <cuda_bf16.h>
#include <cstdint>

// Problem dims
#define B_SZ 64
#define T_SZ 512
#define D_SZ 1024
#define R_SZ 1024
#define O_SZ 1024
#define M_SZ (B_SZ * T_SZ)   // 32768

// ---------------- device scratch (static: no runtime allocation) ----------------
__device__ float          g_xh[(size_t)T_SZ * B_SZ * R_SZ];   // [T][B][R]
__device__ float          g_xz[(size_t)T_SZ * B_SZ * R_SZ];   // [T][B][R]
__device__ float          g_Mz[(size_t)R_SZ * R_SZ];          // Wxz @ Whz
__device__ unsigned short g_x_hi[(size_t)M_SZ * D_SZ];        // X bf16 hi
__device__ unsigned short g_x_lo[(size_t)M_SZ * D_SZ];        // X bf16 lo
__device__ unsigned short g_w_hi[(size_t)2048 * D_SZ];        // [Wxh;Wxz] bf16 hi
__device__ unsigned short g_w_lo[(size_t)2048 * D_SZ];        // [Wxh;Wxz] bf16 lo
__device__ unsigned short g_h_hi[2][B_SZ * R_SZ];             // h bf16 hi (dbl buf)
__device__ unsigned short g_h_lo[2][B_SZ * R_SZ];             // h bf16 lo
__device__ float          g_hf[B_SZ * R_SZ];                  // final h fp32
__device__ unsigned       g_wflag[128 * 32];                  // steps of h written per CTA
__device__ unsigned       g_rflag[128 * 32];                  // steps fully staged per CTA

// ==================== helpers ====================
__device__ __forceinline__ uint32_t smem_u32(const void* p) {
    uint32_t a;
    asm("{ .reg .u64 t; cvta.to.shared.u64 t, %1; cvt.u32.u64 %0, t; }" : "=r"(a) : "l"(p));
    return a;
}
__device__ __forceinline__ void ldsm_x4(uint32_t r[4], uint32_t addr) {
    asm volatile("ldmatrix.sync.aligned.m8n8.x4.shared.b16 {%0,%1,%2,%3}, [%4];"
                 : "=r"(r[0]), "=r"(r[1]), "=r"(r[2]), "=r"(r[3]) : "r"(addr));
}
__device__ __forceinline__ void mma_bf16(float d[4], const uint32_t a[4],
                                         uint32_t b0, uint32_t b1) {
    asm volatile("mma.sync.aligned.m16n8k16.row.col.f32.bf16.bf16.f32 "
                 "{%0,%1,%2,%3}, {%4,%5,%6,%7}, {%8,%9}, {%0,%1,%2,%3};"
                 : "+f"(d[0]), "+f"(d[1]), "+f"(d[2]), "+f"(d[3])
                 : "r"(a[0]), "r"(a[1]), "r"(a[2]), "r"(a[3]), "r"(b0), "r"(b1));
}
__device__ __forceinline__ void cp_async16(uint32_t dst, const void* src) {
    asm volatile("cp.async.cg.shared.global [%0], [%1], 16;" :: "r"(dst), "l"(src));
}
#define CP_COMMIT() asm volatile("cp.async.commit_group;" ::: "memory")
#define CP_WAIT0()  asm volatile("cp.async.wait_group 0;" ::: "memory")
#define BAR_SYNC(id, cnt) asm volatile("bar.sync %0, %1;" :: "r"(id), "r"(cnt) : "memory")

__device__ __forceinline__ uint32_t pack2_hi(float a, float b) {
    return (uint32_t)__bfloat16_as_ushort(__float2bfloat16_rn(a))
         | ((uint32_t)__bfloat16_as_ushort(__float2bfloat16_rn(b)) << 16);
}
__device__ __forceinline__ uint32_t pack2_lo(float a, float b) {
    float ra = a - __bfloat162float(__float2bfloat16_rn(a));
    float rb = b - __bfloat162float(__float2bfloat16_rn(b));
    return pack2_hi(ra, rb);
}

// ==================== init ====================
__global__ void init_kernel() {
    int i = blockIdx.x * blockDim.x + threadIdx.x;
    if (i < B_SZ * R_SZ) { g_h_hi[0][i] = 0; g_h_lo[0][i] = 0; }
    if (i < 128 * 32) { g_wflag[i] = 0u; g_rflag[i] = 0u; }
}

// ==================== fp32 -> bf16 hi/lo split ====================
__global__ void __launch_bounds__(256) split_kernel(const float* __restrict__ src,
                                                    unsigned short* __restrict__ hi,
                                                    unsigned short* __restrict__ lo) {
    size_t i = ((size_t)blockIdx.x * 256 + threadIdx.x) * 4;
    float4 v = *(const float4*)(src + i);
    uint2 h, l;
    h.x = pack2_hi(v.x, v.y); h.y = pack2_hi(v.z, v.w);
    l.x = pack2_lo(v.x, v.y); l.y = pack2_lo(v.z, v.w);
    *(uint2*)(hi + i) = h;
    *(uint2*)(lo + i) = l;
}

// ==================== Mz = Wxz @ Whz (SIMT fp32) ====================
__global__ void __launch_bounds__(256) mz_kernel(const float* __restrict__ Wxz,
                                                 const float* __restrict__ Whz) {
    __shared__ float As[16][68];
    __shared__ float Bs[16][68];
    const int tid = threadIdx.x;
    const int i0 = blockIdx.x * 64;
    const int j0 = blockIdx.y * 64;
    const int tx = tid & 15;
    const int ty = tid >> 4;
    float acc[4][4] = {};

    for (int k0 = 0; k0 < R_SZ; k0 += 16) {
        {
            int row = tid >> 2;
            int c4  = (tid & 3) * 4;
            float4 a = *(const float4*)(Wxz + (size_t)(i0 + row) * R_SZ + k0 + c4);
            As[c4 + 0][row] = a.x; As[c4 + 1][row] = a.y;
            As[c4 + 2][row] = a.z; As[c4 + 3][row] = a.w;
        }
        {
            int kk = tid >> 4;
            int j4 = (tid & 15) * 4;
            float4 b = *(const float4*)(Whz + (size_t)(k0 + kk) * R_SZ + j0 + j4);
            *(float4*)&Bs[kk][j4] = b;
        }
        __syncthreads();
        #pragma unroll
        for (int kk = 0; kk < 16; kk++) {
            float ar[4], br[4];
            *(float4*)ar = *(const float4*)&As[kk][ty * 4];
            *(float4*)br = *(const float4*)&Bs[kk][tx * 4];
            #pragma unroll
            for (int i = 0; i < 4; i++)
                #pragma unroll
                for (int j = 0; j < 4; j++)
                    acc[i][j] = fmaf(ar[i], br[j], acc[i][j]);
        }
        __syncthreads();
    }
    #pragma unroll
    for (int i = 0; i < 4; i++) {
        float4 v = make_float4(acc[i][0], acc[i][1], acc[i][2], acc[i][3]);
        *(float4*)(g_Mz + (size_t)(i0 + ty * 4 + i) * R_SZ + j0 + tx * 4) = v;
    }
}

// ==================== Precompute xh/xz: HMMA, BK=64, ldmatrix B, single-sync ====================
// 128x128 tile, BK=64, 512 threads (16 warps = 4m x 4n), warp tile 32x32.
#define PP_ROW_B 144                         // (64+8) bf16
#define PP_PLANE 18432                       // 128 rows * 144
#define PP_SMEM (8 * PP_PLANE)               // 147456

__global__ void __launch_bounds__(512, 1) precompute_mma(const float* __restrict__ bh_,
                                                         const float* __restrict__ bz_) {
    extern __shared__ char psm[];
    const uint32_t sb = smem_u32(psm);
    const int tid = threadIdx.x, warp = tid >> 5, lane = tid & 31;
    const long m_blk = (long)blockIdx.y * 128;
    const int  n_blk = blockIdx.x * 128;

    const float* bias; float* dst; int rb;
    if (n_blk < R_SZ) { bias = bh_; dst = g_xh; rb = n_blk; }
    else              { bias = bz_; dst = g_xz; rb = n_blk - R_SZ; }

    const int m0w = (warp & 3) * 32;
    const int n0w = (warp >> 2) * 32;

    float acc[2][4][4];
    #pragma unroll
    for (int a = 0; a < 2; a++)
        #pragma unroll
        for (int b = 0; b < 4; b++)
            #pragma unroll
            for (int c = 0; c < 4; c++) acc[a][b][c] = 0.0f;

    auto stage = [&](int buf, int k0) {
        #pragma unroll
        for (int r = 0; r < 2; r++) {
            int item = tid + r * 512;
            int row  = item >> 3;
            int c8   = item & 7;
            size_t sa = (size_t)(m_blk + row) * D_SZ + k0 + c8 * 8;
            size_t sw = (size_t)(n_blk + row) * D_SZ + k0 + c8 * 8;
            uint32_t o = (uint32_t)row * PP_ROW_B + (uint32_t)c8 * 16;
            uint32_t base = sb + (uint32_t)(buf * 4) * PP_PLANE;
            cp_async16(base + o,                g_x_hi + sa);
            cp_async16(base + PP_PLANE + o,     g_x_lo + sa);
            cp_async16(base + 2 * PP_PLANE + o, g_w_hi + sw);
            cp_async16(base + 3 * PP_PLANE + o, g_w_lo + sw);
        }
    };

    const uint32_t b_lm_base = (uint32_t)(lane & 7) * PP_ROW_B + (uint32_t)(lane >> 3) * 16;
    const uint32_t a_lm_base = (uint32_t)(lane & 15) * PP_ROW_B + (uint32_t)(lane >> 4) * 16;

    int buf = 0;
    stage(0, 0);
    CP_COMMIT();
    for (int s = 0; s < D_SZ / 64; s++) {
        CP_WAIT0();
        __syncthreads();
        if (s + 1 < D_SZ / 64) { stage(buf ^ 1, (s + 1) * 64); CP_COMMIT(); }

        const uint32_t AhS = sb + (uint32_t)((buf * 4 + 0) * PP_PLANE);
        const uint32_t AlS = AhS + PP_PLANE;
        const uint32_t BhS = sb + (uint32_t)((buf * 4 + 2) * PP_PLANE);
        const uint32_t BlS = BhS + PP_PLANE;

        #pragma unroll
        for (int k32 = 0; k32 < 2; k32++) {
            uint32_t bh[4][4], bl[4][4];
            #pragma unroll
            for (int ni = 0; ni < 4; ni++) {
                uint32_t bo = (uint32_t)(n0w + ni * 8) * PP_ROW_B + b_lm_base
                            + (uint32_t)k32 * 64;
                ldsm_x4(bh[ni], BhS + bo);
                ldsm_x4(bl[ni], BlS + bo);
            }
            #pragma unroll
            for (int k16 = 0; k16 < 2; k16++) {
                uint32_t ahi[2][4], alo[2][4];
                #pragma unroll
                for (int mi = 0; mi < 2; mi++) {
                    uint32_t ar = (uint32_t)(m0w + mi * 16) * PP_ROW_B + a_lm_base
                                + (uint32_t)k32 * 64 + (uint32_t)k16 * 32;
                    ldsm_x4(ahi[mi], AhS + ar);
                    ldsm_x4(alo[mi], AlS + ar);
                }
                #pragma unroll
                for (int mi = 0; mi < 2; mi++)
                    #pragma unroll
                    for (int ni = 0; ni < 4; ni++) {
                        mma_bf16(acc[mi][ni], ahi[mi], bh[ni][k16 * 2], bh[ni][k16 * 2 + 1]);
                        mma_bf16(acc[mi][ni], ahi[mi], bl[ni][k16 * 2], bl[ni][k16 * 2 + 1]);
                        mma_bf16(acc[mi][ni], alo[mi], bh[ni][k16 * 2], bh[ni][k16 * 2 + 1]);
                    }
            }
        }
        buf ^= 1;
    }

    #pragma unroll
    for (int ni = 0; ni < 4; ni++) {
        int col = n0w + ni * 8 + (lane & 3) * 2;
        float2 bv = *(const float2*)(bias + rb + col);
        #pragma unroll
        for (int mi = 0; mi < 2; mi++) {
            #pragma unroll
            for (int half = 0; half < 2; half++) {
                long m = m_blk + m0w + mi * 16 + (lane >> 2) + half * 8;
                int b = (int)(m >> 9), t = (int)(m & 511);
                float2 v;
                v.x = acc[mi][ni][half * 2 + 0] + bv.x;
                v.y = acc[mi][ni][half * 2 + 1] + bv.y;
                *(float2*)(dst + ((long)t * B_SZ + b) * R_SZ + rb + col) = v;
            }
        }
    }
}

// ==================== Persistent scan: 128 CTAs, producer/consumer flag pipeline ====================
// CTA c: batch half c&1 (rows [32*(c&1), +32)), r-slice [(c>>1)*16, +16).
// 16 warps = 2 m-groups (gid) x 2 K-tiers x 4 roles (q). Tier-group tg (128 thr)
// owns chunks ≡ tier (mod 2), private dbl-buffered A, 1 named barrier/iter.
// Cross-CTA sync: wflag (h written) polled per-warp against the 32 producers of this
// tier's chunks; rflag (staging complete) guards the h double-buffer overwrite.
#define NCTA 128
#define KC 128
#define NCHUNK (R_SZ / KC)                   // 8 total, 4 per tier
#define B_ROW_BYTES 2064                     // (1024+8) bf16
#define A_ROW_BYTES 272                      // (128+8) bf16
#define TG_PLANE (16 * A_ROW_BYTES)          // 4352
#define TG_BUFS (4 * TG_PLANE)               // 17408
#define OFF_BHI 0
#define OFF_BLO (32 * B_ROW_BYTES)           // 66048
#define OFF_A   (2 * 32 * B_ROW_BYTES)       // 132096
#define OFF_RED (OFF_A + 4 * TG_BUFS)        // 201728
#define SCAN_SMEM (OFF_RED + 16 * 32 * 16)   // 209920

__global__ void __launch_bounds__(512) scan_kernel(const float* __restrict__ Whh) {
    extern __shared__ char smem[];
    const uint32_t sbase = smem_u32(smem);
    float4* redbuf = (float4*)(smem + OFF_RED);
    const int tid  = threadIdx.x;
    const int warp = tid >> 5;
    const int lane = tid & 31;
    const int gid  = warp >> 3;
    const int tier = (warp >> 2) & 1;
    const int q    = warp & 3;
    const int tg   = warp >> 2;
    const int gtid = tid & 127;
    const int barid = 1 + tg;
    const int half   = blockIdx.x & 1;
    const int m_base = half * 32;
    const int r_base = (blockIdx.x >> 1) * 16;

    for (int i = tid; i < 32 * R_SZ; i += 512) {
        int j = i >> 10;
        int k = i & 1023;
        float w = (j < 16) ? Whh[(size_t)(r_base + j) * R_SZ + k]
                           : g_Mz[(size_t)(r_base + j - 16) * R_SZ + k];
        __nv_bfloat16 h = __float2bfloat16_rn(w);
        __nv_bfloat16 l = __float2bfloat16_rn(w - __bfloat162float(h));
        *(unsigned short*)(smem + OFF_BHI + j * B_ROW_BYTES + k * 2) = __bfloat16_as_ushort(h);
        *(unsigned short*)(smem + OFF_BLO + j * B_ROW_BYTES + k * 2) = __bfloat16_as_ushort(l);
    }
    __syncthreads();

    const bool is_h = (q < 2);
    const bool gate_owner = (tier == 0) && is_h;

    const int rrow = lane >> 2;
    const int jc   = (lane & 3) * 2;
    const int rc   = (q & 1) * 8 + jc;
    const int jg   = r_base + rc;
    const int lrow0 = gid * 16 + rrow;
    const int lrow1 = lrow0 + 8;
    const int brow0 = m_base + lrow0, brow1 = m_base + lrow1;

    const uint32_t b_lm = (uint32_t)(q * 8 + (lane & 7)) * B_ROW_BYTES
                        + (uint32_t)(lane >> 3) * 16;
    const uint32_t a_row_off = (uint32_t)(lane & 15) * A_ROW_BYTES + (uint32_t)(lane >> 4) * 16;
    const uint32_t tgA = (uint32_t)OFF_A + (uint32_t)tg * TG_BUFS;

    const int w_self = warp;
    const int w_h1 = gid * 8 + 4 + q;
    const int w_z0 = gid * 8 + 0 + (q + 2);
    const int w_z1 = gid * 8 + 4 + (q + 2);

    // wflag producer for this lane: chunk (lane>>3) of this tier -> r-slice j
    const int my_gchunk = 2 * (lane >> 3) + tier;         // 0..7
    const int my_prod   = my_gchunk * 8 + (lane & 7);     // r-slice j 0..63
    volatile unsigned* my_wflag = (volatile unsigned*)&g_wflag[(2 * my_prod + half) * 32];
    volatile unsigned* my_rflag = (tid < 64)
        ? (volatile unsigned*)&g_rflag[(tid * 2 + half) * 32] : (volatile unsigned*)0;
    volatile unsigned* self_rflag = (volatile unsigned*)&g_rflag[blockIdx.x * 32];
    volatile unsigned* self_wflag = (volatile unsigned*)&g_wflag[blockIdx.x * 32];

    float hold[2][2] = {};

    for (int t = 0; t < T_SZ; t++) {
        // ---- A) wait for this tier's producers to have written h(t) ----
        while (*my_wflag < (unsigned)t) { }
        __syncwarp();

        float xh[2][2], xz[2][2];
        if (gate_owner) {
            const float* sh_ = g_xh + (size_t)t * (B_SZ * R_SZ);
            const float* sz_ = g_xz + (size_t)t * (B_SZ * R_SZ);
            float2 a0 = __ldg((const float2*)(sh_ + (size_t)brow0 * R_SZ + jg));
            float2 a1 = __ldg((const float2*)(sh_ + (size_t)brow1 * R_SZ + jg));
            float2 c0 = __ldg((const float2*)(sz_ + (size_t)brow0 * R_SZ + jg));
            float2 c1 = __ldg((const float2*)(sz_ + (size_t)brow1 * R_SZ + jg));
            xh[0][0]=a0.x; xh[0][1]=a0.y; xh[1][0]=a1.x; xh[1][1]=a1.y;
            xz[0][0]=c0.x; xz[0][1]=c0.y; xz[1][0]=c1.x; xz[1][1]=c1.y;
        }

        const unsigned short* hhi = g_h_hi[t & 1];
        const unsigned short* hlo = g_h_lo[t & 1];

        float d0[4] = {0.f, 0.f, 0.f, 0.f};
        float d1[4] = {0.f, 0.f, 0.f, 0.f};

        auto stage = [&](int buf, int i) {
            const int kc = (2 * i + tier) * KC;
            #pragma unroll
            for (int r = 0; r < 4; r++) {
                int cid   = gtid + r * 128;
                int plane = cid >> 8;
                int rem   = cid & 255;
                int row   = rem >> 4;
                int c16   = rem & 15;
                uint32_t dA = sbase + tgA + (uint32_t)buf * (2 * TG_PLANE)
                            + (uint32_t)plane * TG_PLANE
                            + (uint32_t)row * A_ROW_BYTES + (uint32_t)c16 * 16;
                const unsigned short* sp = plane ? hlo : hhi;
                cp_async16(dA, sp + (size_t)(m_base + gid * 16 + row) * R_SZ + kc + c16 * 8);
            }
        };

        stage(0, 0);
        CP_COMMIT();
        for (int i = 0; i < NCHUNK / 2; i++) {
            CP_WAIT0();
            BAR_SYNC(barid, 128);
            if (i + 1 < NCHUNK / 2) { stage((i + 1) & 1, i + 1); CP_COMMIT(); }

            const int buf = i & 1;
            const int chunk = 2 * i + tier;
            const uint32_t a_hi_base = sbase + tgA + (uint32_t)buf * (2 * TG_PLANE);
            const uint32_t a_lo_base = a_hi_base + TG_PLANE;
            const uint32_t kB_chunk = (uint32_t)(chunk * KC) * 2;

            #pragma unroll
            for (int kb2 = 0; kb2 < KC / 32; kb2++) {
                const uint32_t kloc = (uint32_t)kb2 * 64;
                uint32_t ahA[4], ahB[4], alA[4], alB[4];
                ldsm_x4(ahA, a_hi_base + a_row_off + kloc);
                ldsm_x4(ahB, a_hi_base + a_row_off + kloc + 32);
                ldsm_x4(alA, a_lo_base + a_row_off + kloc);
                ldsm_x4(alB, a_lo_base + a_row_off + kloc + 32);

                uint32_t bh[4], bl[4];
                ldsm_x4(bh, sbase + OFF_BHI + b_lm + kB_chunk + kloc);
                ldsm_x4(bl, sbase + OFF_BLO + b_lm + kB_chunk + kloc);

                mma_bf16(d0, ahA, bh[0], bh[1]);
                mma_bf16(d1, ahB, bh[2], bh[3]);
                mma_bf16(d0, ahA, bl[0], bl[1]);
                mma_bf16(d1, ahB, bl[2], bl[3]);
                mma_bf16(d0, alA, bh[0], bh[1]);
                mma_bf16(d1, alB, bh[2], bh[3]);
            }
        }

        // ---- C) K-tier reduction ----
        float4 dq;
        dq.x = d0[0] + d1[0]; dq.y = d0[1] + d1[1];
        dq.z = d0[2] + d1[2]; dq.w = d0[3] + d1[3];
        redbuf[w_self * 32 + lane] = dq;
        __syncthreads();   // all staging (cp.async) and redbuf writes complete

        // ---- D) publish "staging done"; wait for consumers of h(t-1)'s buffer ----
        if (tid == 0) *self_rflag = (unsigned)(t + 1);
        if (tid < 64) {
            while (*my_rflag < (unsigned)t) { }
        }
        __syncthreads();

        // ---- E) gate + h(t+1) write ----
        if (gate_owner) {
            float4 dh1 = redbuf[w_h1 * 32 + lane];
            float4 dz0 = redbuf[w_z0 * 32 + lane];
            float4 dz1 = redbuf[w_z1 * 32 + lane];
            float dh[4] = { dq.x + dh1.x, dq.y + dh1.y, dq.z + dh1.z, dq.w + dh1.w };
            float dz[4] = { dz0.x + dz1.x, dz0.y + dz1.y, dz0.z + dz1.z, dz0.w + dz1.w };

            unsigned short* dhi = g_h_hi[(t + 1) & 1];
            unsigned short* dlo = g_h_lo[(t + 1) & 1];
            #pragma unroll
            for (int qq = 0; qq < 2; qq++) {
                int br = (qq == 0) ? brow0 : brow1;
                float hn[2];
                #pragma unroll
                for (int cc = 0; cc < 2; cc++) {
                    float pre_h = dh[qq * 2 + cc] + xh[qq][cc];
                    float pre_z = dz[qq * 2 + cc] + xz[qq][cc];
                    float z  = 1.0f / (1.0f + expf(-pre_z));
                    float hb = fmaxf(pre_h, 0.0f);
                    hn[cc] = z * hold[qq][cc] + (1.0f - z) * hb;
                    hold[qq][cc] = hn[cc];
                }
                size_t o = (size_t)br * R_SZ + jg;
                *(uint32_t*)(dhi + o) = pack2_hi(hn[0], hn[1]);
                *(uint32_t*)(dlo + o) = pack2_lo(hn[0], hn[1]);
                if (t == T_SZ - 1) {
                    g_hf[o] = hn[0]; g_hf[o + 1] = hn[1];
                }
            }
        }

        // ---- F) publish h(t+1) written ----
        __threadfence();
        __syncthreads();
        if (tid == 0) *self_wflag = (unsigned)(t + 1);
    }
}

// ==================== Output: y = h_final @ Wy^T + by ====================
__global__ void __launch_bounds__(128) output_kernel(const float* __restrict__ Wy,
                                                     const float* __restrict__ by,
                                                     float* __restrict__ out) {
    __shared__ float shh[R_SZ];
    const int b = blockIdx.x;
    const int o = blockIdx.y * 128 + threadIdx.x;
    const float* hrow = g_hf + (size_t)b * R_SZ;
    #pragma unroll
    for (int v = 0; v < 2; v++) {
        int i4 = threadIdx.x + v * 128;
        ((float4*)shh)[i4] = *(const float4*)(hrow + i4 * 4);
    }
    __syncthreads();
    float acc = __ldg(&by[o]);
    const float* wrow = Wy + (size_t)o * R_SZ;
    #pragma unroll 8
    for (int k4 = 0; k4 < R_SZ / 4; k4++) {
        float4 h4 = ((const float4*)shh)[k4];
        float4 w4 = __ldg((const float4*)(wrow + k4 * 4));
        acc = fmaf(h4.x, w4.x, acc); acc = fmaf(h4.y, w4.y, acc);
        acc = fmaf(h4.z, w4.z, acc); acc = fmaf(h4.w, w4.w, acc);
    }
    out[(size_t)b * O_SZ + o] = acc;
}

// ==================== launch ====================
extern "C" void kernel_launch(void* const* d_in, const int* in_sizes, int n_in,
                              void* d_out, int out_size) {
    const float* x   = (const float*)d_in[0];
    const float* Wxh = (const float*)d_in[1];
    const float* bh  = (const float*)d_in[2];
    const float* Whh = (const float*)d_in[3];
    const float* Wxz = (const float*)d_in[4];
    const float* bz  = (const float*)d_in[5];
    const float* Whz = (const float*)d_in[6];
    const float* Wy  = (const float*)d_in[7];
    const float* by  = (const float*)d_in[8];
    float* out = (float*)d_out;

    static bool attr_set = false;
    if (!attr_set) {
        cudaFuncSetAttribute(scan_kernel,
                             cudaFuncAttributeMaxDynamicSharedMemorySize, SCAN_SMEM);
        cudaFuncSetAttribute(precompute_mma,
                             cudaFuncAttributeMaxDynamicSharedMemorySize, PP_SMEM);
        attr_set = true;
    }

    unsigned short *xhi_p, *xlo_p, *whi_p, *wlo_p;
    cudaGetSymbolAddress((void**)&xhi_p, g_x_hi);
    cudaGetSymbolAddress((void**)&xlo_p, g_x_lo);
    cudaGetSymbolAddress((void**)&whi_p, g_w_hi);
    cudaGetSymbolAddress((void**)&wlo_p, g_w_lo);
    split_kernel<<<(int)((size_t)M_SZ * D_SZ / 1024), 256>>>(x, xhi_p, xlo_p);
    split_kernel<<<(R_SZ * D_SZ) / 1024, 256>>>(Wxh, whi_p, wlo_p);
    split_kernel<<<(R_SZ * D_SZ) / 1024, 256>>>(Wxz, whi_p + (size_t)R_SZ * D_SZ,
                                                wlo_p + (size_t)R_SZ * D_SZ);

    precompute_mma<<<dim3(2048 / 128, M_SZ / 128), 512, PP_SMEM>>>(bh, bz);
    mz_kernel<<<dim3(R_SZ / 64, R_SZ / 64), 256>>>(Wxz, Whz);
    init_kernel<<<(B_SZ * R_SZ + 255) / 256, 256>>>();
    scan_kernel<<<NCTA, 512, SCAN_SMEM>>>(Whh);
    output_kernel<<<dim3(B_SZ, O_SZ / 128), 128>>>(Wy, by, out);
}

// round 16
// speedup vs baseline: 1.0498x; 1.0498x over previous
#include <cuda_runtime.h>
#include <cuda_bf16.h>
#include <cstdint>

// Problem dims
#define B_SZ 64
#define T_SZ 512
#define D_SZ 1024
#define R_SZ 1024
#define O_SZ 1024
#define M_SZ (B_SZ * T_SZ)   // 32768

// ---------------- device scratch (static: no runtime allocation) ----------------
__device__ float          g_xh[(size_t)T_SZ * B_SZ * R_SZ];   // [T][B][R]
__device__ float          g_xz[(size_t)T_SZ * B_SZ * R_SZ];   // [T][B][R]
__device__ float          g_Mz[(size_t)R_SZ * R_SZ];          // Wxz @ Whz
__device__ unsigned short g_x_hi[(size_t)M_SZ * D_SZ];        // X bf16 hi
__device__ unsigned short g_x_lo[(size_t)M_SZ * D_SZ];        // X bf16 lo
__device__ unsigned short g_w_hi[(size_t)2048 * D_SZ];        // [Wxh;Wxz] bf16 hi
__device__ unsigned short g_w_lo[(size_t)2048 * D_SZ];        // [Wxh;Wxz] bf16 lo
__device__ unsigned short g_h_hi[2][B_SZ * R_SZ];             // h bf16 hi (dbl buf)
__device__ unsigned short g_h_lo[2][B_SZ * R_SZ];             // h bf16 lo
__device__ float          g_hf[B_SZ * R_SZ];                  // final h fp32
__device__ unsigned       g_flags[128 * 32];                  // padded per-CTA step flags

// ==================== helpers ====================
__device__ __forceinline__ uint32_t smem_u32(const void* p) {
    uint32_t a;
    asm("{ .reg .u64 t; cvta.to.shared.u64 t, %1; cvt.u32.u64 %0, t; }" : "=r"(a) : "l"(p));
    return a;
}
__device__ __forceinline__ void ldsm_x4(uint32_t r[4], uint32_t addr) {
    asm volatile("ldmatrix.sync.aligned.m8n8.x4.shared.b16 {%0,%1,%2,%3}, [%4];"
                 : "=r"(r[0]), "=r"(r[1]), "=r"(r[2]), "=r"(r[3]) : "r"(addr));
}
__device__ __forceinline__ void mma_bf16(float d[4], const uint32_t a[4],
                                         uint32_t b0, uint32_t b1) {
    asm volatile("mma.sync.aligned.m16n8k16.row.col.f32.bf16.bf16.f32 "
                 "{%0,%1,%2,%3}, {%4,%5,%6,%7}, {%8,%9}, {%0,%1,%2,%3};"
                 : "+f"(d[0]), "+f"(d[1]), "+f"(d[2]), "+f"(d[3])
                 : "r"(a[0]), "r"(a[1]), "r"(a[2]), "r"(a[3]), "r"(b0), "r"(b1));
}
__device__ __forceinline__ void cp_async16(uint32_t dst, const void* src) {
    asm volatile("cp.async.cg.shared.global [%0], [%1], 16;" :: "r"(dst), "l"(src));
}
#define CP_COMMIT() asm volatile("cp.async.commit_group;" ::: "memory")
#define CP_WAIT0()  asm volatile("cp.async.wait_group 0;" ::: "memory")
#define BAR_SYNC(id, cnt) asm volatile("bar.sync %0, %1;" :: "r"(id), "r"(cnt) : "memory")

__device__ __forceinline__ uint32_t pack2_hi(float a, float b) {
    return (uint32_t)__bfloat16_as_ushort(__float2bfloat16_rn(a))
         | ((uint32_t)__bfloat16_as_ushort(__float2bfloat16_rn(b)) << 16);
}
__device__ __forceinline__ uint32_t pack2_lo(float a, float b) {
    float ra = a - __bfloat162float(__float2bfloat16_rn(a));
    float rb = b - __bfloat162float(__float2bfloat16_rn(b));
    return pack2_hi(ra, rb);
}

// ==================== init ====================
__global__ void init_kernel() {
    int i = blockIdx.x * blockDim.x + threadIdx.x;
    if (i < B_SZ * R_SZ) { g_h_hi[0][i] = 0; g_h_lo[0][i] = 0; }
    if (i < 128 * 32) g_flags[i] = 0u;
}

// ==================== fused fp32 -> bf16 hi/lo split (X, Wxh, Wxz) ====================
// Blocks [0, 32768): X. [32768, 33792): Wxh -> g_w rows [0,1024).
// [33792, 34816): Wxz -> g_w rows [1024,2048).
#define SPLIT_X_BLOCKS (M_SZ * D_SZ / 1024)        // 32768
#define SPLIT_W_BLOCKS (R_SZ * D_SZ / 1024)        // 1024
__global__ void __launch_bounds__(256) split_all_kernel(const float* __restrict__ x,
                                                        const float* __restrict__ Wxh,
                                                        const float* __restrict__ Wxz) {
    const float* src;
    unsigned short *hi, *lo;
    size_t base;
    int b = blockIdx.x;
    if (b < SPLIT_X_BLOCKS) {
        src = x; hi = g_x_hi; lo = g_x_lo; base = (size_t)b * 1024;
    } else if (b < SPLIT_X_BLOCKS + SPLIT_W_BLOCKS) {
        src = Wxh; hi = g_w_hi; lo = g_w_lo;
        base = (size_t)(b - SPLIT_X_BLOCKS) * 1024;
    } else {
        src = Wxz; hi = g_w_hi + (size_t)R_SZ * D_SZ; lo = g_w_lo + (size_t)R_SZ * D_SZ;
        base = (size_t)(b - SPLIT_X_BLOCKS - SPLIT_W_BLOCKS) * 1024;
    }
    size_t i = base + (size_t)threadIdx.x * 4;
    float4 v = *(const float4*)(src + (i - base));
    v = *(const float4*)(src + i);   // overwrite: correct absolute index
    uint2 h, l;
    h.x = pack2_hi(v.x, v.y); h.y = pack2_hi(v.z, v.w);
    l.x = pack2_lo(v.x, v.y); l.y = pack2_lo(v.z, v.w);
    *(uint2*)(hi + i) = h;
    *(uint2*)(lo + i) = l;
}

// ==================== Mz = Wxz @ Whz (SIMT fp32) ====================
__global__ void __launch_bounds__(256) mz_kernel(const float* __restrict__ Wxz,
                                                 const float* __restrict__ Whz) {
    __shared__ float As[16][68];
    __shared__ float Bs[16][68];
    const int tid = threadIdx.x;
    const int i0 = blockIdx.x * 64;
    const int j0 = blockIdx.y * 64;
    const int tx = tid & 15;
    const int ty = tid >> 4;
    float acc[4][4] = {};

    for (int k0 = 0; k0 < R_SZ; k0 += 16) {
        {
            int row = tid >> 2;
            int c4  = (tid & 3) * 4;
            float4 a = *(const float4*)(Wxz + (size_t)(i0 + row) * R_SZ + k0 + c4);
            As[c4 + 0][row] = a.x; As[c4 + 1][row] = a.y;
            As[c4 + 2][row] = a.z; As[c4 + 3][row] = a.w;
        }
        {
            int kk = tid >> 4;
            int j4 = (tid & 15) * 4;
            float4 b = *(const float4*)(Whz + (size_t)(k0 + kk) * R_SZ + j0 + j4);
            *(float4*)&Bs[kk][j4] = b;
        }
        __syncthreads();
        #pragma unroll
        for (int kk = 0; kk < 16; kk++) {
            float ar[4], br[4];
            *(float4*)ar = *(const float4*)&As[kk][ty * 4];
            *(float4*)br = *(const float4*)&Bs[kk][tx * 4];
            #pragma unroll
            for (int i = 0; i < 4; i++)
                #pragma unroll
                for (int j = 0; j < 4; j++)
                    acc[i][j] = fmaf(ar[i], br[j], acc[i][j]);
        }
        __syncthreads();
    }
    #pragma unroll
    for (int i = 0; i < 4; i++) {
        float4 v = make_float4(acc[i][0], acc[i][1], acc[i][2], acc[i][3]);
        *(float4*)(g_Mz + (size_t)(i0 + ty * 4 + i) * R_SZ + j0 + tx * 4) = v;
    }
}

// ==================== Precompute xh/xz: HMMA, BK=64, ldmatrix B, single-sync ====================
// 128x128 tile, BK=64, 512 threads (16 warps = 4m x 4n), warp tile 32x32.
#define PP_ROW_B 144                         // (64+8) bf16
#define PP_PLANE 18432                       // 128 rows * 144
#define PP_SMEM (8 * PP_PLANE)               // 147456

__global__ void __launch_bounds__(512, 1) precompute_mma(const float* __restrict__ bh_,
                                                         const float* __restrict__ bz_) {
    extern __shared__ char psm[];
    const uint32_t sb = smem_u32(psm);
    const int tid = threadIdx.x, warp = tid >> 5, lane = tid & 31;
    const long m_blk = (long)blockIdx.y * 128;
    const int  n_blk = blockIdx.x * 128;

    const float* bias; float* dst; int rb;
    if (n_blk < R_SZ) { bias = bh_; dst = g_xh; rb = n_blk; }
    else              { bias = bz_; dst = g_xz; rb = n_blk - R_SZ; }

    const int m0w = (warp & 3) * 32;
    const int n0w = (warp >> 2) * 32;

    float acc[2][4][4];
    #pragma unroll
    for (int a = 0; a < 2; a++)
        #pragma unroll
        for (int b = 0; b < 4; b++)
            #pragma unroll
            for (int c = 0; c < 4; c++) acc[a][b][c] = 0.0f;

    auto stage = [&](int buf, int k0) {
        #pragma unroll
        for (int r = 0; r < 2; r++) {
            int item = tid + r * 512;
            int row  = item >> 3;
            int c8   = item & 7;
            size_t sa = (size_t)(m_blk + row) * D_SZ + k0 + c8 * 8;
            size_t sw = (size_t)(n_blk + row) * D_SZ + k0 + c8 * 8;
            uint32_t o = (uint32_t)row * PP_ROW_B + (uint32_t)c8 * 16;
            uint32_t base = sb + (uint32_t)(buf * 4) * PP_PLANE;
            cp_async16(base + o,                g_x_hi + sa);
            cp_async16(base + PP_PLANE + o,     g_x_lo + sa);
            cp_async16(base + 2 * PP_PLANE + o, g_w_hi + sw);
            cp_async16(base + 3 * PP_PLANE + o, g_w_lo + sw);
        }
    };

    const uint32_t b_lm_base = (uint32_t)(lane & 7) * PP_ROW_B + (uint32_t)(lane >> 3) * 16;
    const uint32_t a_lm_base = (uint32_t)(lane & 15) * PP_ROW_B + (uint32_t)(lane >> 4) * 16;

    int buf = 0;
    stage(0, 0);
    CP_COMMIT();
    for (int s = 0; s < D_SZ / 64; s++) {
        CP_WAIT0();
        __syncthreads();
        if (s + 1 < D_SZ / 64) { stage(buf ^ 1, (s + 1) * 64); CP_COMMIT(); }

        const uint32_t AhS = sb + (uint32_t)((buf * 4 + 0) * PP_PLANE);
        const uint32_t AlS = AhS + PP_PLANE;
        const uint32_t BhS = sb + (uint32_t)((buf * 4 + 2) * PP_PLANE);
        const uint32_t BlS = BhS + PP_PLANE;

        #pragma unroll
        for (int k32 = 0; k32 < 2; k32++) {
            uint32_t bh[4][4], bl[4][4];
            #pragma unroll
            for (int ni = 0; ni < 4; ni++) {
                uint32_t bo = (uint32_t)(n0w + ni * 8) * PP_ROW_B + b_lm_base
                            + (uint32_t)k32 * 64;
                ldsm_x4(bh[ni], BhS + bo);
                ldsm_x4(bl[ni], BlS + bo);
            }
            #pragma unroll
            for (int k16 = 0; k16 < 2; k16++) {
                uint32_t ahi[2][4], alo[2][4];
                #pragma unroll
                for (int mi = 0; mi < 2; mi++) {
                    uint32_t ar = (uint32_t)(m0w + mi * 16) * PP_ROW_B + a_lm_base
                                + (uint32_t)k32 * 64 + (uint32_t)k16 * 32;
                    ldsm_x4(ahi[mi], AhS + ar);
                    ldsm_x4(alo[mi], AlS + ar);
                }
                #pragma unroll
                for (int mi = 0; mi < 2; mi++)
                    #pragma unroll
                    for (int ni = 0; ni < 4; ni++) {
                        mma_bf16(acc[mi][ni], ahi[mi], bh[ni][k16 * 2], bh[ni][k16 * 2 + 1]);
                        mma_bf16(acc[mi][ni], ahi[mi], bl[ni][k16 * 2], bl[ni][k16 * 2 + 1]);
                        mma_bf16(acc[mi][ni], alo[mi], bh[ni][k16 * 2], bh[ni][k16 * 2 + 1]);
                    }
            }
        }
        buf ^= 1;
    }

    #pragma unroll
    for (int ni = 0; ni < 4; ni++) {
        int col = n0w + ni * 8 + (lane & 3) * 2;
        float2 bv = *(const float2*)(bias + rb + col);
        #pragma unroll
        for (int mi = 0; mi < 2; mi++) {
            #pragma unroll
            for (int half = 0; half < 2; half++) {
                long m = m_blk + m0w + mi * 16 + (lane >> 2) + half * 8;
                int b = (int)(m >> 9), t = (int)(m & 511);
                float2 v;
                v.x = acc[mi][ni][half * 2 + 0] + bv.x;
                v.y = acc[mi][ni][half * 2 + 1] + bv.y;
                *(float2*)(dst + ((long)t * B_SZ + b) * R_SZ + rb + col) = v;
            }
        }
    }
}

// ==================== Persistent scan: 128 CTAs, K-split tiers, per-half barrier ====================
// CTA c: batch half c&1 (rows [32*(c&1), +32)), r-slice [(c>>1)*16, +16).
// 16 warps = 2 m-groups (gid) x 2 K-tiers x 4 roles (q). Tier-group tg (128 thr)
// owns chunks ≡ tier (mod 2), private dbl-buffered A, 1 named barrier/iter.
// Grid barrier: two independent 64-CTA domains (one per batch half).
#define NCTA 128
#define KC 128
#define NCHUNK (R_SZ / KC)                   // 8 total, 4 per tier
#define B_ROW_BYTES 2064                     // (1024+8) bf16
#define A_ROW_BYTES 272                      // (128+8) bf16
#define TG_PLANE (16 * A_ROW_BYTES)          // 4352
#define TG_BUFS (4 * TG_PLANE)               // 17408
#define OFF_BHI 0
#define OFF_BLO (32 * B_ROW_BYTES)           // 66048
#define OFF_A   (2 * 32 * B_ROW_BYTES)       // 132096
#define OFF_RED (OFF_A + 4 * TG_BUFS)        // 201728
#define SCAN_SMEM (OFF_RED + 16 * 32 * 16)   // 209920

__global__ void __launch_bounds__(512) scan_kernel(const float* __restrict__ Whh) {
    extern __shared__ char smem[];
    const uint32_t sbase = smem_u32(smem);
    float4* redbuf = (float4*)(smem + OFF_RED);
    const int tid  = threadIdx.x;
    const int warp = tid >> 5;
    const int lane = tid & 31;
    const int gid  = warp >> 3;
    const int tier = (warp >> 2) & 1;
    const int q    = warp & 3;
    const int tg   = warp >> 2;
    const int gtid = tid & 127;
    const int barid = 1 + tg;
    const int half   = blockIdx.x & 1;
    const int m_base = half * 32;
    const int r_base = (blockIdx.x >> 1) * 16;

    for (int i = tid; i < 32 * R_SZ; i += 512) {
        int j = i >> 10;
        int k = i & 1023;
        float w = (j < 16) ? Whh[(size_t)(r_base + j) * R_SZ + k]
                           : g_Mz[(size_t)(r_base + j - 16) * R_SZ + k];
        __nv_bfloat16 h = __float2bfloat16_rn(w);
        __nv_bfloat16 l = __float2bfloat16_rn(w - __bfloat162float(h));
        *(unsigned short*)(smem + OFF_BHI + j * B_ROW_BYTES + k * 2) = __bfloat16_as_ushort(h);
        *(unsigned short*)(smem + OFF_BLO + j * B_ROW_BYTES + k * 2) = __bfloat16_as_ushort(l);
    }
    __syncthreads();

    const bool is_h = (q < 2);
    const bool gate_owner = (tier == 0) && is_h;

    const int rrow = lane >> 2;
    const int jc   = (lane & 3) * 2;
    const int rc   = (q & 1) * 8 + jc;
    const int jg   = r_base + rc;
    const int lrow0 = gid * 16 + rrow;
    const int lrow1 = lrow0 + 8;
    const int brow0 = m_base + lrow0, brow1 = m_base + lrow1;

    const uint32_t b_lm = (uint32_t)(q * 8 + (lane & 7)) * B_ROW_BYTES
                        + (uint32_t)(lane >> 3) * 16;
    const uint32_t a_row_off = (uint32_t)(lane & 15) * A_ROW_BYTES + (uint32_t)(lane >> 4) * 16;
    const uint32_t tgA = (uint32_t)OFF_A + (uint32_t)tg * TG_BUFS;

    const int w_self = warp;
    const int w_h1 = gid * 8 + 4 + q;
    const int w_z0 = gid * 8 + 0 + (q + 2);
    const int w_z1 = gid * 8 + 4 + (q + 2);

    volatile unsigned* flags = (volatile unsigned*)g_flags;

    float hold[2][2] = {};

    for (int t = 0; t < T_SZ; t++) {
        float xh[2][2], xz[2][2];
        if (gate_owner) {
            const float* sh_ = g_xh + (size_t)t * (B_SZ * R_SZ);
            const float* sz_ = g_xz + (size_t)t * (B_SZ * R_SZ);
            float2 a0 = __ldg((const float2*)(sh_ + (size_t)brow0 * R_SZ + jg));
            float2 a1 = __ldg((const float2*)(sh_ + (size_t)brow1 * R_SZ + jg));
            float2 c0 = __ldg((const float2*)(sz_ + (size_t)brow0 * R_SZ + jg));
            float2 c1 = __ldg((const float2*)(sz_ + (size_t)brow1 * R_SZ + jg));
            xh[0][0]=a0.x; xh[0][1]=a0.y; xh[1][0]=a1.x; xh[1][1]=a1.y;
            xz[0][0]=c0.x; xz[0][1]=c0.y; xz[1][0]=c1.x; xz[1][1]=c1.y;
        }

        const unsigned short* hhi = g_h_hi[t & 1];
        const unsigned short* hlo = g_h_lo[t & 1];

        float d0[4] = {0.f, 0.f, 0.f, 0.f};
        float d1[4] = {0.f, 0.f, 0.f, 0.f};

        auto stage = [&](int buf, int i) {
            const int kc = (2 * i + tier) * KC;
            #pragma unroll
            for (int r = 0; r < 4; r++) {
                int cid   = gtid + r * 128;
                int plane = cid >> 8;
                int rem   = cid & 255;
                int row   = rem >> 4;
                int c16   = rem & 15;
                uint32_t dA = sbase + tgA + (uint32_t)buf * (2 * TG_PLANE)
                            + (uint32_t)plane * TG_PLANE
                            + (uint32_t)row * A_ROW_BYTES + (uint32_t)c16 * 16;
                const unsigned short* sp = plane ? hlo : hhi;
                cp_async16(dA, sp + (size_t)(m_base + gid * 16 + row) * R_SZ + kc + c16 * 8);
            }
        };

        stage(0, 0);
        CP_COMMIT();
        for (int i = 0; i < NCHUNK / 2; i++) {
            CP_WAIT0();
            BAR_SYNC(barid, 128);
            if (i + 1 < NCHUNK / 2) { stage((i + 1) & 1, i + 1); CP_COMMIT(); }

            const int buf = i & 1;
            const int chunk = 2 * i + tier;
            const uint32_t a_hi_base = sbase + tgA + (uint32_t)buf * (2 * TG_PLANE);
            const uint32_t a_lo_base = a_hi_base + TG_PLANE;
            const uint32_t kB_chunk = (uint32_t)(chunk * KC) * 2;

            #pragma unroll
            for (int kb2 = 0; kb2 < KC / 32; kb2++) {
                const uint32_t kloc = (uint32_t)kb2 * 64;
                uint32_t ahA[4], ahB[4], alA[4], alB[4];
                ldsm_x4(ahA, a_hi_base + a_row_off + kloc);
                ldsm_x4(ahB, a_hi_base + a_row_off + kloc + 32);
                ldsm_x4(alA, a_lo_base + a_row_off + kloc);
                ldsm_x4(alB, a_lo_base + a_row_off + kloc + 32);

                uint32_t bh[4], bl[4];
                ldsm_x4(bh, sbase + OFF_BHI + b_lm + kB_chunk + kloc);
                ldsm_x4(bl, sbase + OFF_BLO + b_lm + kB_chunk + kloc);

                mma_bf16(d0, ahA, bh[0], bh[1]);
                mma_bf16(d1, ahB, bh[2], bh[3]);
                mma_bf16(d0, ahA, bl[0], bl[1]);
                mma_bf16(d1, ahB, bl[2], bl[3]);
                mma_bf16(d0, alA, bh[0], bh[1]);
                mma_bf16(d1, alB, bh[2], bh[3]);
            }
        }

        float4 dq;
        dq.x = d0[0] + d1[0]; dq.y = d0[1] + d1[1];
        dq.z = d0[2] + d1[2]; dq.w = d0[3] + d1[3];
        redbuf[w_self * 32 + lane] = dq;
        __syncthreads();

        if (gate_owner) {
            float4 dh1 = redbuf[w_h1 * 32 + lane];
            float4 dz0 = redbuf[w_z0 * 32 + lane];
            float4 dz1 = redbuf[w_z1 * 32 + lane];
            float dh[4] = { dq.x + dh1.x, dq.y + dh1.y, dq.z + dh1.z, dq.w + dh1.w };
            float dz[4] = { dz0.x + dz1.x, dz0.y + dz1.y, dz0.z + dz1.z, dz0.w + dz1.w };

            unsigned short* dhi = g_h_hi[(t + 1) & 1];
            unsigned short* dlo = g_h_lo[(t + 1) & 1];
            #pragma unroll
            for (int qq = 0; qq < 2; qq++) {
                int br = (qq == 0) ? brow0 : brow1;
                float hn[2];
                #pragma unroll
                for (int cc = 0; cc < 2; cc++) {
                    float pre_h = dh[qq * 2 + cc] + xh[qq][cc];
                    float pre_z = dz[qq * 2 + cc] + xz[qq][cc];
                    float z  = 1.0f / (1.0f + expf(-pre_z));
                    float hb = fmaxf(pre_h, 0.0f);
                    hn[cc] = z * hold[qq][cc] + (1.0f - z) * hb;
                    hold[qq][cc] = hn[cc];
                }
                size_t o = (size_t)br * R_SZ + jg;
                *(uint32_t*)(dhi + o) = pack2_hi(hn[0], hn[1]);
                *(uint32_t*)(dlo + o) = pack2_lo(hn[0], hn[1]);
                if (t == T_SZ - 1) {
                    g_hf[o] = hn[0]; g_hf[o + 1] = hn[1];
                }
            }
        }

        // per-half grid barrier: 64 CTAs with same batch half (x & 1 == half)
        __threadfence();
        __syncthreads();
        if (tid == 0) flags[blockIdx.x * 32] = (unsigned)(t + 1);
        if (tid < 64) {
            while (flags[(tid * 2 + half) * 32] <= (unsigned)t) { }
        }
        __syncthreads();
    }
}

// ==================== Output: y = h_final @ Wy^T + by ====================
__global__ void __launch_bounds__(128) output_kernel(const float* __restrict__ Wy,
                                                     const float* __restrict__ by,
                                                     float* __restrict__ out) {
    __shared__ float shh[R_SZ];
    const int b = blockIdx.x;
    const int o = blockIdx.y * 128 + threadIdx.x;
    const float* hrow = g_hf + (size_t)b * R_SZ;
    #pragma unroll
    for (int v = 0; v < 2; v++) {
        int i4 = threadIdx.x + v * 128;
        ((float4*)shh)[i4] = *(const float4*)(hrow + i4 * 4);
    }
    __syncthreads();
    float acc = __ldg(&by[o]);
    const float* wrow = Wy + (size_t)o * R_SZ;
    #pragma unroll 8
    for (int k4 = 0; k4 < R_SZ / 4; k4++) {
        float4 h4 = ((const float4*)shh)[k4];
        float4 w4 = __ldg((const float4*)(wrow + k4 * 4));
        acc = fmaf(h4.x, w4.x, acc); acc = fmaf(h4.y, w4.y, acc);
        acc = fmaf(h4.z, w4.z, acc); acc = fmaf(h4.w, w4.w, acc);
    }
    out[(size_t)b * O_SZ + o] = acc;
}

// ==================== launch ====================
extern "C" void kernel_launch(void* const* d_in, const int* in_sizes, int n_in,
                              void* d_out, int out_size) {
    const float* x   = (const float*)d_in[0];
    const float* Wxh = (const float*)d_in[1];
    const float* bh  = (const float*)d_in[2];
    const float* Whh = (const float*)d_in[3];
    const float* Wxz = (const float*)d_in[4];
    const float* bz  = (const float*)d_in[5];
    const float* Whz = (const float*)d_in[6];
    const float* Wy  = (const float*)d_in[7];
    const float* by  = (const float*)d_in[8];
    float* out = (float*)d_out;

    static bool attr_set = false;
    if (!attr_set) {
        cudaFuncSetAttribute(scan_kernel,
                             cudaFuncAttributeMaxDynamicSharedMemorySize, SCAN_SMEM);
        cudaFuncSetAttribute(precompute_mma,
                             cudaFuncAttributeMaxDynamicSharedMemorySize, PP_SMEM);
        attr_set = true;
    }

    // fused bf16 hi/lo split for X, Wxh, Wxz
    split_all_kernel<<<SPLIT_X_BLOCKS + 2 * SPLIT_W_BLOCKS, 256>>>(x, Wxh, Wxz);

    precompute_mma<<<dim3(2048 / 128, M_SZ / 128), 512, PP_SMEM>>>(bh, bz);
    mz_kernel<<<dim3(R_SZ / 64, R_SZ / 64), 256>>>(Wxz, Whz);
    init_kernel<<<(B_SZ * R_SZ + 255) / 256, 256>>>();
    scan_kernel<<<NCTA, 512, SCAN_SMEM>>>(Whh);
    output_kernel<<<dim3(B_SZ, O_SZ / 128), 128>>>(Wy, by, out);
}